// round 1
// baseline (speedup 1.0000x reference)
#include <cuda_runtime.h>

// ShapeletNet: sliding squared-euclidean distance + per-segment min + minmax scale + Linear(1,2)
//
// dist[p] = ||q||^2 + XX[p] - 2*QX[p]
//   QX[p] = sum_{d,j} X[d][p+j] * q[d][j]   (the big GEMM-like part)
//   XX[p] = sum_{t=p..p+M-1} sum_d X[d][t]^2
//
// Kernel 1: one block per segment. Register-blocked f32x2 (FFMA2) GEMM computing
//           S[t][j] = <X[:,t], q[:,j]> for the 512 x 32 tile, then a deterministic
//           diagonal-gather for QX, fused dist + min reduction.
// Kernel 2: one block; global min/max over segment-mins, scale, linear layer.

#define DFEAT 64
#define MLEN 32
#define TILE_T 512
#define DCHUNK 32
#define NTHREADS 256

typedef unsigned long long ull;

__device__ __forceinline__ ull fma2(ull a, ull b, ull c) {
    ull d;
    asm("fma.rn.f32x2 %0, %1, %2, %3;" : "=l"(d) : "l"(a), "l"(b), "l"(c));
    return d;
}
__device__ __forceinline__ ull dup2(float x) {
    ull d; unsigned xi = __float_as_uint(x);
    asm("mov.b64 %0, {%1, %1};" : "=l"(d) : "r"(xi));
    return d;
}
__device__ __forceinline__ float2 unpack2(ull v) {
    unsigned lo, hi;
    asm("mov.b64 {%0, %1}, %2;" : "=r"(lo), "=r"(hi) : "l"(v));
    return make_float2(__uint_as_float(lo), __uint_as_float(hi));
}

__device__ float g_mins[8192];

extern __shared__ __align__(16) float smem_dyn[];

__global__ __launch_bounds__(NTHREADS, 2)
void seg_min_kernel(const float* __restrict__ X,
                    const float* __restrict__ q,
                    const int* __restrict__ cumlens,
                    long long T)
{
    // ---- shared memory layout ----
    float* Xs   = smem_dyn;                      // DCHUNK * TILE_T     (16384 f)
    float* qs   = Xs + DCHUNK * TILE_T;          // DFEAT * MLEN        ( 2048 f)
    float* cs2  = qs + DFEAT * MLEN;             // TILE_T              (  512 f)
    float* part = cs2 + TILE_T;                  // NTHREADS * 16       ( 4096 f)
    float* red  = part + NTHREADS * 16;          // 16 f scratch

    const int seg = blockIdx.x;
    const long long c0 = (long long)cumlens[seg];
    int len = cumlens[seg + 1] - (int)c0;
    if (len > TILE_T) len = TILE_T;
    if (len < 0) len = 0;

    const int tid = threadIdx.x;
    const int a = tid >> 2;        // t-group: 64 groups of 8 t
    const int b = tid & 3;         // j-group: 4 groups of 8 j
    const int t0 = a * 8;
    const int j0 = b * 8;

    // load query into smem; zero cs2
    for (int i = tid; i < DFEAT * MLEN; i += NTHREADS) qs[i] = q[i];
    cs2[tid] = 0.f;
    cs2[tid + NTHREADS] = 0.f;
    __syncthreads();

    // ---- QQ = sum(q^2), deterministic block reduce ----
    float qq = 0.f;
#pragma unroll
    for (int i = 0; i < 8; i++) { float v = qs[tid * 8 + i]; qq = fmaf(v, v, qq); }
#pragma unroll
    for (int o = 16; o; o >>= 1) qq += __shfl_down_sync(0xffffffffu, qq, o);
    if ((tid & 31) == 0) red[tid >> 5] = qq;
    __syncthreads();
    float QQ = 0.f;
#pragma unroll
    for (int w = 0; w < NTHREADS / 32; w++) QQ += red[w];

    // ---- main GEMM: S[t][j], 8t x 8j per thread, packed f32x2 ----
    ull acc2[4][8];
#pragma unroll
    for (int i = 0; i < 4; i++)
#pragma unroll
        for (int j = 0; j < 8; j++) acc2[i][j] = 0ull;

    for (int dbase = 0; dbase < DFEAT; dbase += DCHUNK) {
        __syncthreads();   // protect Xs before overwrite
        // stage DCHUNK rows of X (zero-padded past segment end)
        for (int i = tid; i < DCHUNK * TILE_T; i += NTHREADS) {
            int dd = i >> 9;       // /TILE_T
            int t  = i & (TILE_T - 1);
            float v = 0.f;
            if (t < len) v = X[(long long)(dbase + dd) * T + c0 + t];
            Xs[i] = v;
        }
        __syncthreads();

        // accumulate column squared-sums
        for (int tt = tid; tt < TILE_T; tt += NTHREADS) {
            float s = 0.f;
#pragma unroll
            for (int dd = 0; dd < DCHUNK; dd++) {
                float v = Xs[dd * TILE_T + tt];
                s = fmaf(v, v, s);
            }
            cs2[tt] += s;
        }

        // register-blocked GEMM over this d-chunk
#pragma unroll 4
        for (int dd = 0; dd < DCHUNK; dd++) {
            const ulonglong2* xr = (const ulonglong2*)(Xs + dd * TILE_T + t0);
            ulonglong2 xa = xr[0], xb = xr[1];
            ull xp0 = xa.x, xp1 = xa.y, xp2 = xb.x, xp3 = xb.y;

            const float4* qr = (const float4*)(qs + (dbase + dd) * MLEN + j0);
            float4 q0 = qr[0], q1 = qr[1];
            ull qd[8];
            qd[0] = dup2(q0.x); qd[1] = dup2(q0.y); qd[2] = dup2(q0.z); qd[3] = dup2(q0.w);
            qd[4] = dup2(q1.x); qd[5] = dup2(q1.y); qd[6] = dup2(q1.z); qd[7] = dup2(q1.w);

#pragma unroll
            for (int j = 0; j < 8; j++) {
                acc2[0][j] = fma2(xp0, qd[j], acc2[0][j]);
                acc2[1][j] = fma2(xp1, qd[j], acc2[1][j]);
                acc2[2][j] = fma2(xp2, qd[j], acc2[2][j]);
                acc2[3][j] = fma2(xp3, qd[j], acc2[3][j]);
            }
        }
    }

    // ---- per-thread diagonal partial sums: ps[delta+7], delta = i - j in [-7,7] ----
    float ps[15];
#pragma unroll
    for (int k = 0; k < 15; k++) ps[k] = 0.f;
#pragma unroll
    for (int i2 = 0; i2 < 4; i2++) {
#pragma unroll
        for (int j = 0; j < 8; j++) {
            float2 u = unpack2(acc2[i2][j]);
            ps[(2 * i2)     - j + 7] += u.x;
            ps[(2 * i2 + 1) - j + 7] += u.y;
        }
    }
#pragma unroll
    for (int k = 0; k < 15; k++) part[tid * 16 + k] = ps[k];
    __syncthreads();

    // ---- gather QX[p] (deterministic order), dist, per-thread min ----
    const int nwin = len - MLEN + 1;
    float lmin = 3e38f;
    for (int p = tid; p < TILE_T; p += NTHREADS) {
        if (p < nwin) {
            int glo = p >> 3;
            int ghi = (p + 7) >> 3;
            float qx = 0.f;
            for (int g = glo; g <= ghi; ++g) {
                int del = p - (g << 3) + 7;   // 0..14
#pragma unroll
                for (int bb = 0; bb < 4; ++bb) {
                    int aa = g + bb;
                    if (aa < 64) qx += part[(aa * 4 + bb) * 16 + del];
                }
            }
            float xx = 0.f;
#pragma unroll
            for (int j = 0; j < MLEN; j++) xx += cs2[p + j];
            float dist = QQ + xx - 2.f * qx;
            lmin = fminf(lmin, dist);
        }
    }
#pragma unroll
    for (int o = 16; o; o >>= 1) lmin = fminf(lmin, __shfl_down_sync(0xffffffffu, lmin, o));
    if ((tid & 31) == 0) red[tid >> 5] = lmin;
    __syncthreads();
    if (tid == 0) {
        float m = red[0];
#pragma unroll
        for (int w = 1; w < NTHREADS / 32; w++) m = fminf(m, red[w]);
        g_mins[seg] = m;
    }
}

__global__ void finalize_kernel(const float* __restrict__ lin_w,
                                const float* __restrict__ lin_b,
                                float* __restrict__ out, int n_seg)
{
    __shared__ float slo[32], shi[32];
    __shared__ float flo, fhi;
    const int tid = threadIdx.x;

    float lo = 3e38f, hi = -3e38f;
    for (int i = tid; i < n_seg; i += blockDim.x) {
        float v = g_mins[i];
        lo = fminf(lo, v);
        hi = fmaxf(hi, v);
    }
#pragma unroll
    for (int o = 16; o; o >>= 1) {
        lo = fminf(lo, __shfl_down_sync(0xffffffffu, lo, o));
        hi = fmaxf(hi, __shfl_down_sync(0xffffffffu, hi, o));
    }
    if ((tid & 31) == 0) { slo[tid >> 5] = lo; shi[tid >> 5] = hi; }
    __syncthreads();
    if (tid == 0) {
        int nw = (blockDim.x + 31) >> 5;
        float l = slo[0], h = shi[0];
        for (int w = 1; w < nw; w++) { l = fminf(l, slo[w]); h = fmaxf(h, shi[w]); }
        flo = l; fhi = h;
    }
    __syncthreads();

    const float w0 = lin_w[0], w1 = lin_w[1];
    const float b0 = lin_b[0], b1 = lin_b[1];
    const float inv = 1.f / (fhi - flo + 1e-16f);
    for (int i = tid; i < n_seg; i += blockDim.x) {
        float s = (g_mins[i] - flo) * inv;
        out[2 * i]     = fmaf(s, w0, b0);
        out[2 * i + 1] = fmaf(s, w1, b1);
    }
}

extern "C" void kernel_launch(void* const* d_in, const int* in_sizes, int n_in,
                              void* d_out, int out_size)
{
    const float* X   = (const float*)d_in[0];
    const float* q   = (const float*)d_in[1];
    const float* lw  = (const float*)d_in[2];
    const float* lb  = (const float*)d_in[3];
    const int*   cum = (const int*)d_in[4];

    const int n_seg = in_sizes[4] - 1;
    const long long T = (long long)in_sizes[0] / DFEAT;

    const size_t smem = (size_t)(DCHUNK * TILE_T + DFEAT * MLEN + TILE_T +
                                 NTHREADS * 16 + 16) * sizeof(float);
    cudaFuncSetAttribute(seg_min_kernel,
                         cudaFuncAttributeMaxDynamicSharedMemorySize, (int)smem);

    seg_min_kernel<<<n_seg, NTHREADS, smem>>>(X, q, cum, T);
    finalize_kernel<<<1, 1024>>>(lw, lb, (float*)d_out, n_seg);
}

// round 2
// speedup vs baseline: 1.2347x; 1.2347x over previous
#include <cuda_runtime.h>

// ShapeletNet fused single-kernel version.
// dist[p] = ||q||^2 + XX[p] - 2*QX[p],  QX[p] = sum_{d,j} X[d][p+j]*q[d][j]
// One block per segment (512 threads). Register-blocked f32x2 GEMM computes
// S[t][j] = <X[:,t], q[:,j]> for the 512x32 tile (8t x 4j per thread),
// diagonal-gather gives QX, fused dist+min. Last finished block does the
// global min/max + Linear(1,2) epilogue (deterministic: min/max are
// order-independent).

#define DFEAT 64
#define MLEN 32
#define TT 512
#define DCH 32
#define NT 512
#define PSTRIDE 13   // 11 diagonal slots padded to odd stride -> conflict-free

typedef unsigned long long ull;

__device__ __forceinline__ ull fma2(ull a, ull b, ull c) {
    ull d;
    asm("fma.rn.f32x2 %0, %1, %2, %3;" : "=l"(d) : "l"(a), "l"(b), "l"(c));
    return d;
}
__device__ __forceinline__ ull dup2(float x) {
    ull d; unsigned xi = __float_as_uint(x);
    asm("mov.b64 %0, {%1, %1};" : "=l"(d) : "r"(xi));
    return d;
}
__device__ __forceinline__ float2 unpack2(ull v) {
    unsigned lo, hi;
    asm("mov.b64 {%0, %1}, %2;" : "=r"(lo), "=r"(hi) : "l"(v));
    return make_float2(__uint_as_float(lo), __uint_as_float(hi));
}

__device__ float g_mins[8192];
__device__ int   g_count;     // zero at load; self-reset each launch

extern __shared__ __align__(16) float sm[];

__global__ __launch_bounds__(NT, 2)
void shapelet_kernel(const float* __restrict__ X,
                     const float* __restrict__ q,
                     const int* __restrict__ cumlens,
                     const float* __restrict__ lin_w,
                     const float* __restrict__ lin_b,
                     float* __restrict__ out,
                     long long T, int n_seg)
{
    // smem layout: [Xs | qs | cs2 | red]; part-table aliases Xs (disjoint phases)
    float* Xs   = sm;                      // DCH*TT = 16384 floats
    float* part = sm;                      // NT*PSTRIDE = 6656 floats (alias)
    float* qs   = sm + DCH * TT;           // 2048
    float* cs2  = qs + DFEAT * MLEN;       // 512
    float* red  = cs2 + TT;                // 34 scratch

    const int seg = blockIdx.x;
    const long long c0 = (long long)cumlens[seg];
    int len = cumlens[seg + 1] - (int)c0;
    if (len > TT) len = TT;
    if (len < 0) len = 0;

    const int tid = threadIdx.x;
    const int g = tid >> 3;          // t-group: 64 groups of 8 t
    const int h = tid & 7;           // j-group: 8 groups of 4 j
    const int t0 = g * 8;
    const int j0 = h * 4;

    // load query to smem
    for (int i = tid; i < DFEAT * MLEN; i += NT) qs[i] = q[i];
    __syncthreads();

    // QQ = sum(q^2), deterministic block reduce (held in register per thread)
    float qq = 0.f;
#pragma unroll
    for (int i = 0; i < 4; i++) { float v = qs[tid * 4 + i]; qq = fmaf(v, v, qq); }
#pragma unroll
    for (int o = 16; o; o >>= 1) qq += __shfl_down_sync(0xffffffffu, qq, o);
    if ((tid & 31) == 0) red[tid >> 5] = qq;
    __syncthreads();
    float QQ = 0.f;
#pragma unroll
    for (int w = 0; w < NT / 32; w++) QQ += red[w];

    // ---- main GEMM: S[t][j], 8t x 4j per thread, packed f32x2 ----
    ull acc2[4][4];
#pragma unroll
    for (int i = 0; i < 4; i++)
#pragma unroll
        for (int j = 0; j < 4; j++) acc2[i][j] = 0ull;

    for (int dbase = 0; dbase < DFEAT; dbase += DCH) {
        __syncthreads();   // everyone done reading Xs (or QQ phase) before overwrite
        // stage DCH rows (one element per thread per row), zero-padded
        {
            const float* xp = X + (long long)dbase * T + c0 + tid;
            const bool ok = (tid < len);
#pragma unroll 8
            for (int dd = 0; dd < DCH; dd++) {
                float v = ok ? xp[(long long)dd * T] : 0.f;
                Xs[dd * TT + tid] = v;
            }
        }
        __syncthreads();

        // column squared-sums (conflict-free: column = tid)
        {
            float s = 0.f;
#pragma unroll
            for (int dd = 0; dd < DCH; dd++) {
                float v = Xs[dd * TT + tid];
                s = fmaf(v, v, s);
            }
            cs2[tid] = (dbase == 0) ? s : (cs2[tid] + s);
        }

        // register-blocked GEMM over this d-chunk
#pragma unroll 4
        for (int dd = 0; dd < DCH; dd++) {
            const ulonglong2* xr = (const ulonglong2*)(Xs + dd * TT + t0);
            ulonglong2 xa = xr[0], xb = xr[1];       // x pairs: t0..t0+7

            const float4 qv = *(const float4*)(qs + (dbase + dd) * MLEN + j0);
            ull qd0 = dup2(qv.x), qd1 = dup2(qv.y), qd2 = dup2(qv.z), qd3 = dup2(qv.w);

            acc2[0][0] = fma2(xa.x, qd0, acc2[0][0]);
            acc2[1][0] = fma2(xa.y, qd0, acc2[1][0]);
            acc2[2][0] = fma2(xb.x, qd0, acc2[2][0]);
            acc2[3][0] = fma2(xb.y, qd0, acc2[3][0]);
            acc2[0][1] = fma2(xa.x, qd1, acc2[0][1]);
            acc2[1][1] = fma2(xa.y, qd1, acc2[1][1]);
            acc2[2][1] = fma2(xb.x, qd1, acc2[2][1]);
            acc2[3][1] = fma2(xb.y, qd1, acc2[3][1]);
            acc2[0][2] = fma2(xa.x, qd2, acc2[0][2]);
            acc2[1][2] = fma2(xa.y, qd2, acc2[1][2]);
            acc2[2][2] = fma2(xb.x, qd2, acc2[2][2]);
            acc2[3][2] = fma2(xb.y, qd2, acc2[3][2]);
            acc2[0][3] = fma2(xa.x, qd3, acc2[0][3]);
            acc2[1][3] = fma2(xa.y, qd3, acc2[1][3]);
            acc2[2][3] = fma2(xb.x, qd3, acc2[2][3]);
            acc2[3][3] = fma2(xb.y, qd3, acc2[3][3]);
        }
    }
    __syncthreads();   // GEMM done; Xs region can be reused as part-table

    // per-thread diagonal partials: delta = i - j in [-3, 7] -> 11 slots
    {
        float ps[11];
#pragma unroll
        for (int k = 0; k < 11; k++) ps[k] = 0.f;
#pragma unroll
        for (int i2 = 0; i2 < 4; i2++) {
#pragma unroll
            for (int jj = 0; jj < 4; jj++) {
                float2 u = unpack2(acc2[i2][jj]);
                ps[(2 * i2)     - jj + 3] += u.x;
                ps[(2 * i2 + 1) - jj + 3] += u.y;
            }
        }
#pragma unroll
        for (int k = 0; k < 11; k++) part[tid * PSTRIDE + k] = ps[k];
    }
    __syncthreads();

    // gather QX[p], dist, per-thread min (one window per thread)
    const int nwin = len - MLEN + 1;
    float lmin = 3e38f;
    {
        const int p = tid;
        if (p < nwin) {
            float xx = 0.f;
#pragma unroll
            for (int j = 0; j < MLEN; j++) xx += cs2[p + j];
            float qx = 0.f;
#pragma unroll
            for (int hh = 0; hh < 8; hh++) {
                int base = p + 4 * hh;            // = p + j0 of group hh
                int a0 = base >> 3;               // ceil((base-7)/8) for base>=0
                int a1 = (base + 3) >> 3;
                if (a1 > 63) a1 = 63;
                for (int a = a0; a <= a1; ++a) {
                    int del = base - 8 * a;       // in [-3, 7]
                    qx += part[(a * 8 + hh) * PSTRIDE + del + 3];
                }
            }
            lmin = QQ + xx - 2.f * qx;
        }
    }
#pragma unroll
    for (int o = 16; o; o >>= 1) lmin = fminf(lmin, __shfl_down_sync(0xffffffffu, lmin, o));
    if ((tid & 31) == 0) red[tid >> 5] = lmin;
    __syncthreads();
    if (tid == 0) {
        float m = red[0];
#pragma unroll
        for (int w = 1; w < NT / 32; w++) m = fminf(m, red[w]);
        g_mins[seg] = m;
    }

    // ---- last-block-done epilogue ----
    __shared__ int s_islast;
    __threadfence();
    __syncthreads();
    if (tid == 0) {
        int old = atomicAdd(&g_count, 1);
        s_islast = (old == gridDim.x - 1) ? 1 : 0;
    }
    __syncthreads();
    if (!s_islast) return;
    __threadfence();   // acquire: make all blocks' g_mins visible

    float lo = 3e38f, hi = -3e38f;
    for (int i = tid; i < n_seg; i += NT) {
        float v = g_mins[i];
        lo = fminf(lo, v);
        hi = fmaxf(hi, v);
    }
#pragma unroll
    for (int o = 16; o; o >>= 1) {
        lo = fminf(lo, __shfl_down_sync(0xffffffffu, lo, o));
        hi = fmaxf(hi, __shfl_down_sync(0xffffffffu, hi, o));
    }
    if ((tid & 31) == 0) { red[tid >> 5] = lo; red[16 + (tid >> 5)] = hi; }
    __syncthreads();
    if (tid == 0) {
        float l = red[0], hh2 = red[16];
#pragma unroll
        for (int w = 1; w < NT / 32; w++) { l = fminf(l, red[w]); hh2 = fmaxf(hh2, red[16 + w]); }
        red[32] = l; red[33] = hh2;
        g_count = 0;   // self-reset for next graph replay
    }
    __syncthreads();
    const float flo = red[32], fhi = red[33];
    const float w0 = lin_w[0], w1 = lin_w[1];
    const float b0 = lin_b[0], b1 = lin_b[1];
    const float inv = 1.f / (fhi - flo + 1e-16f);
    for (int i = tid; i < n_seg; i += NT) {
        float s = (g_mins[i] - flo) * inv;
        out[2 * i]     = fmaf(s, w0, b0);
        out[2 * i + 1] = fmaf(s, w1, b1);
    }
}

extern "C" void kernel_launch(void* const* d_in, const int* in_sizes, int n_in,
                              void* d_out, int out_size)
{
    const float* X   = (const float*)d_in[0];
    const float* q   = (const float*)d_in[1];
    const float* lw  = (const float*)d_in[2];
    const float* lb  = (const float*)d_in[3];
    const int*   cum = (const int*)d_in[4];

    const int n_seg = in_sizes[4] - 1;
    const long long T = (long long)in_sizes[0] / DFEAT;

    const size_t smem = (size_t)(DCH * TT + DFEAT * MLEN + TT + 64) * sizeof(float);
    cudaFuncSetAttribute(shapelet_kernel,
                         cudaFuncAttributeMaxDynamicSharedMemorySize, (int)smem);

    shapelet_kernel<<<n_seg, NT, smem>>>(X, q, cum, lw, lb, (float*)d_out, T, n_seg);
}

// round 4
// speedup vs baseline: 1.2931x; 1.0474x over previous
#include <cuda_runtime.h>
#include <cstdint>

// ShapeletNet, FFMA2 (f32x2) register-blocked GEMM with cp.async double-buffered
// staging. One block per segment (512 thr). S[t][j] = <X[:,t], q[:,j]> via
// 8t x 4j per-thread accumulators; diagonal gather -> dist -> segment min;
// last-done block does minmax scale + Linear(1,2).

#define DFEAT 64
#define MLEN 32
#define TT 512
#define NT 512
#define DCH 16          // d-rows per pipeline chunk
#define NCHUNK 4
#define PSTRIDE 13      // diag partial table stride (odd -> conflict-free)

// float-index offsets in dynamic smem
#define XS_OFF   0          // 2 * DCH * TT = 16384 floats (double buffer)
#define QD_OFF   16384      // qdup: 2048 ull = 4096 floats
#define CS2_OFF  20480      // 512 floats
#define RED_OFF  20992      // 40 floats
#define SMEM_FLOATS 21032   // ~84.1 KB -> 2 blocks/SM

typedef unsigned long long ull;

__device__ __forceinline__ ull fma2(ull a, ull b, ull c) {
    ull d;
    asm("fma.rn.f32x2 %0, %1, %2, %3;" : "=l"(d) : "l"(a), "l"(b), "l"(c));
    return d;
}
__device__ __forceinline__ float2 unpack2(ull v) {
    unsigned lo, hi;
    asm("mov.b64 {%0, %1}, %2;" : "=r"(lo), "=r"(hi) : "l"(v));
    return make_float2(__uint_as_float(lo), __uint_as_float(hi));
}
__device__ __forceinline__ uint32_t smem_u32(const void* p) {
    uint32_t a;
    asm("{ .reg .u64 t; cvta.to.shared.u64 t, %1; cvt.u32.u64 %0, t; }" : "=r"(a) : "l"(p));
    return a;
}
#define CP_ASYNC16(dst, src, sz) \
    asm volatile("cp.async.cg.shared.global [%0], [%1], 16, %2;" \
                 :: "r"(dst), "l"(src), "r"(sz) : "memory")
#define CP_COMMIT()  asm volatile("cp.async.commit_group;" ::: "memory")
#define CP_WAIT1()   asm volatile("cp.async.wait_group 1;" ::: "memory")
#define CP_WAIT0()   asm volatile("cp.async.wait_group 0;" ::: "memory")

__device__ float g_mins[8192];
__device__ int   g_count;

extern __shared__ __align__(16) float smf[];

// cp.async staging of one chunk (16 rows x 512 floats), zero-fill past len
__device__ __forceinline__ void stage_async(const float* __restrict__ X, long long T,
                                            long long c0, int len, int tid, int dbase,
                                            uint32_t buf_u32)
{
    const int col = tid & 127;            // 16B unit within row
    const int r0  = tid >> 7;             // 0..3
    int vb = len * 4 - col * 16;          // valid bytes from this col
    int sz = vb < 0 ? 0 : (vb > 16 ? 16 : vb);
    const char* gbase = (const char*)(X + c0) + (size_t)col * 16;
#pragma unroll
    for (int k = 0; k < 4; k++) {
        int dd = r0 + 4 * k;
        uint32_t daddr = buf_u32 + (uint32_t)(dd * TT * 4 + col * 16);
        const char* g = gbase + (long long)(dbase + dd) * T * 4;
        CP_ASYNC16(daddr, g, sz);
    }
}

// scalar fallback (misaligned c0)
__device__ __forceinline__ void stage_scalar(const float* __restrict__ X, long long T,
                                             long long c0, int len, int tid, int dbase,
                                             float* buf)
{
    for (int i = tid; i < DCH * TT; i += NT) {
        int dd = i >> 9;
        int t  = i & (TT - 1);
        buf[i] = (t < len) ? X[(long long)(dbase + dd) * T + c0 + t] : 0.f;
    }
}

__global__ __launch_bounds__(NT, 2)
void shapelet_kernel(const float* __restrict__ X,
                     const float* __restrict__ q,
                     const int* __restrict__ cumlens,
                     const float* __restrict__ lin_w,
                     const float* __restrict__ lin_b,
                     float* __restrict__ out,
                     long long T, int n_seg)
{
    float* Xs   = smf + XS_OFF;
    ull*   qd   = (ull*)(smf + QD_OFF);
    float* cs2p = smf + CS2_OFF;
    float* redf = smf + RED_OFF;
    float* part = smf;                    // aliases Xs (disjoint phases)
    const uint32_t xs_u32 = smem_u32(Xs);

    const int tid = threadIdx.x;
    const int w = tid >> 5;
    const int lane = tid & 31;
    const int t0 = (tid >> 3) * 8;        // t-group base
    const int j0 = (tid & 7) * 4;         // j-group base (in ull units == j index)

    const int seg = blockIdx.x;
    const long long c0 = (long long)cumlens[seg];
    int len = cumlens[seg + 1] - (int)c0;
    if (len > TT) len = TT;
    if (len < 0) len = 0;

    const bool aligned = ((c0 & 3) == 0);

    // kick off chunk 0 copy immediately
    if (aligned) { stage_async(X, T, c0, len, tid, 0, xs_u32); CP_COMMIT(); }
    else         stage_scalar(X, T, c0, len, tid, 0, Xs);

    // build duplicated-q table + QQ
    float qq = 0.f;
#pragma unroll
    for (int k = 0; k < 4; k++) {
        int i = tid + k * NT;             // 0..2047
        float v = q[i];
        qq = fmaf(v, v, qq);
        ull p = ((ull)__float_as_uint(v) << 32) | __float_as_uint(v);
        qd[i] = p;
    }
#pragma unroll
    for (int o = 16; o; o >>= 1) qq += __shfl_down_sync(0xffffffffu, qq, o);
    if (lane == 0) redf[w] = qq;
    __syncthreads();
    float QQ = 0.f;
#pragma unroll
    for (int ww = 0; ww < NT / 32; ww++) QQ += redf[ww];

    // ---- pipelined chunks ----
    ull acc2[4][4];
#pragma unroll
    for (int i = 0; i < 4; i++)
#pragma unroll
        for (int j = 0; j < 4; j++) acc2[i][j] = 0ull;

    float cs = 0.f;

#pragma unroll
    for (int c = 0; c < NCHUNK; c++) {
        // issue next chunk's copy into the other buffer
        if (c + 1 < NCHUNK) {
            if (aligned) {
                stage_async(X, T, c0, len, tid, (c + 1) * DCH,
                            xs_u32 + (uint32_t)(((c + 1) & 1) * DCH * TT * 4));
                CP_COMMIT();
            } else {
                stage_scalar(X, T, c0, len, tid, (c + 1) * DCH,
                             Xs + ((c + 1) & 1) * DCH * TT);
            }
        }
        if (aligned) { if (c + 1 < NCHUNK) CP_WAIT1(); else CP_WAIT0(); }
        __syncthreads();

        const float* xb = Xs + (c & 1) * DCH * TT;
        const ull* qrow = qd + (c * DCH) * MLEN + j0;

        // column squared-sums for this chunk
        {
            float s = cs;
#pragma unroll
            for (int dd = 0; dd < DCH; dd++) {
                float v = xb[dd * TT + tid];
                s = fmaf(v, v, s);
            }
            cs = s;
        }

        // GEMM over 16 d-rows
#pragma unroll
        for (int dd = 0; dd < DCH; dd++) {
            const ulonglong2* xr = (const ulonglong2*)(xb + dd * TT + t0);
            ulonglong2 xa = xr[0], xv = xr[1];
            const ulonglong2* qr = (const ulonglong2*)(qrow + dd * MLEN);
            ulonglong2 qa = qr[0], qb = qr[1];

            acc2[0][0] = fma2(xa.x, qa.x, acc2[0][0]);
            acc2[1][0] = fma2(xa.y, qa.x, acc2[1][0]);
            acc2[2][0] = fma2(xv.x, qa.x, acc2[2][0]);
            acc2[3][0] = fma2(xv.y, qa.x, acc2[3][0]);
            acc2[0][1] = fma2(xa.x, qa.y, acc2[0][1]);
            acc2[1][1] = fma2(xa.y, qa.y, acc2[1][1]);
            acc2[2][1] = fma2(xv.x, qa.y, acc2[2][1]);
            acc2[3][1] = fma2(xv.y, qa.y, acc2[3][1]);
            acc2[0][2] = fma2(xa.x, qb.x, acc2[0][2]);
            acc2[1][2] = fma2(xa.y, qb.x, acc2[1][2]);
            acc2[2][2] = fma2(xv.x, qb.x, acc2[2][2]);
            acc2[3][2] = fma2(xv.y, qb.x, acc2[3][2]);
            acc2[0][3] = fma2(xa.x, qb.y, acc2[0][3]);
            acc2[1][3] = fma2(xa.y, qb.y, acc2[1][3]);
            acc2[2][3] = fma2(xv.x, qb.y, acc2[2][3]);
            acc2[3][3] = fma2(xv.y, qb.y, acc2[3][3]);
        }
        __syncthreads();   // buffer (c&1) may be overwritten next iteration
    }

    cs2p[tid] = cs;

    // per-thread diagonal partials: delta = i - j in [-3, 7] -> 11 slots
    {
        float ps[11];
#pragma unroll
        for (int k = 0; k < 11; k++) ps[k] = 0.f;
#pragma unroll
        for (int i2 = 0; i2 < 4; i2++) {
#pragma unroll
            for (int jj = 0; jj < 4; jj++) {
                float2 u = unpack2(acc2[i2][jj]);
                ps[(2 * i2)     - jj + 3] += u.x;
                ps[(2 * i2 + 1) - jj + 3] += u.y;
            }
        }
#pragma unroll
        for (int k = 0; k < 11; k++) part[tid * PSTRIDE + k] = ps[k];
    }
    __syncthreads();

    // gather QX[p], dist, per-thread min (one window per thread)
    const int nwin = len - MLEN + 1;
    float lmin = 3e38f;
    {
        const int p = tid;
        if (p < nwin) {
            float xx = 0.f;
#pragma unroll
            for (int j = 0; j < MLEN; j++) xx += cs2p[p + j];
            float qx = 0.f;
#pragma unroll
            for (int hh = 0; hh < 8; hh++) {
                int base = p + 4 * hh;
                int a0 = base >> 3;
                int a1 = (base + 3) >> 3;
                if (a1 > 63) a1 = 63;
                for (int a = a0; a <= a1; ++a) {
                    int del = base - 8 * a;      // in [-3, 7]
                    qx += part[(a * 8 + hh) * PSTRIDE + del + 3];
                }
            }
            lmin = QQ + xx - 2.f * qx;
        }
    }
#pragma unroll
    for (int o = 16; o; o >>= 1) lmin = fminf(lmin, __shfl_down_sync(0xffffffffu, lmin, o));
    __syncthreads();
    if (lane == 0) redf[w] = lmin;
    __syncthreads();
    if (tid == 0) {
        float m = redf[0];
#pragma unroll
        for (int ww = 1; ww < NT / 32; ww++) m = fminf(m, redf[ww]);
        g_mins[seg] = m;
    }

    // ---- last-block-done epilogue ----
    int* flagp = (int*)(redf + 33);
    __threadfence();
    __syncthreads();
    if (tid == 0) {
        int old = atomicAdd(&g_count, 1);
        *flagp = (old == gridDim.x - 1) ? 1 : 0;
    }
    __syncthreads();
    if (!*flagp) return;
    __threadfence();

    float lo = 3e38f, hi = -3e38f;
    for (int i = tid; i < n_seg; i += NT) {
        float v = g_mins[i];
        lo = fminf(lo, v);
        hi = fmaxf(hi, v);
    }
#pragma unroll
    for (int o = 16; o; o >>= 1) {
        lo = fminf(lo, __shfl_down_sync(0xffffffffu, lo, o));
        hi = fmaxf(hi, __shfl_down_sync(0xffffffffu, hi, o));
    }
    __syncthreads();
    if (lane == 0) { redf[w] = lo; redf[16 + w] = hi; }
    __syncthreads();
    if (tid == 0) {
        float l = redf[0], h = redf[16];
#pragma unroll
        for (int ww = 1; ww < NT / 32; ww++) { l = fminf(l, redf[ww]); h = fmaxf(h, redf[16 + ww]); }
        redf[34] = l; redf[35] = h;
        g_count = 0;   // self-reset for next graph replay
    }
    __syncthreads();
    const float flo = redf[34], fhi = redf[35];
    const float w0 = lin_w[0], w1 = lin_w[1];
    const float b0 = lin_b[0], b1 = lin_b[1];
    const float inv = 1.f / (fhi - flo + 1e-16f);
    for (int i = tid; i < n_seg; i += NT) {
        float s = (g_mins[i] - flo) * inv;
        out[2 * i]     = fmaf(s, w0, b0);
        out[2 * i + 1] = fmaf(s, w1, b1);
    }
}

extern "C" void kernel_launch(void* const* d_in, const int* in_sizes, int n_in,
                              void* d_out, int out_size)
{
    const float* X   = (const float*)d_in[0];
    const float* q   = (const float*)d_in[1];
    const float* lw  = (const float*)d_in[2];
    const float* lb  = (const float*)d_in[3];
    const int*   cum = (const int*)d_in[4];

    const int n_seg = in_sizes[4] - 1;
    const long long T = (long long)in_sizes[0] / DFEAT;

    const size_t smem = SMEM_FLOATS * sizeof(float);
    cudaFuncSetAttribute(shapelet_kernel,
                         cudaFuncAttributeMaxDynamicSharedMemorySize, (int)smem);

    shapelet_kernel<<<n_seg, NT, smem>>>(X, q, cum, lw, lb, (float*)d_out, T, n_seg);
}

// round 5
// speedup vs baseline: 1.6808x; 1.2998x over previous
#include <cuda_runtime.h>
#include <cstdint>

// ShapeletNet, FFMA2 diagonal-pair GEMM. One block per segment (256 thr).
// Each thread owns an 8t x 8j tile of S[t][j] = <X[:,t], q[:,j]> but
// accumulates directly into 14 diagonal buckets (delta = t-j) using packed
// f32x2 FMAs whose two lanes always share the same delta:
//   aligned pair:  (x[2i],x[2i+1])   * (q[2k],q[2k+1]) -> delta 2(i-k)
//   shifted pair:  (x[2i+1],x[2i+2]) * (q[2k],q[2k+1]) -> delta 2(i-k)+1
// QX[p] gather reads ~8 bucket entries; dist = QQ + XX - 2QX; segment min;
// last-done block does minmax scale + Linear(1,2).

#define DFEAT 64
#define MLEN 32
#define TT 512
#define NT 256
#define DCH 16
#define NCHUNK 4
#define XSTR 528        // padded row stride (16 zero floats for x[t0+8] reads)
#define PSTRIDE 15      // 14 bucket slots padded to odd stride

// float-index offsets in dynamic smem
#define XS_OFF   0                  // 2 * DCH * XSTR = 16896 floats
#define QS_OFF   16896              // 2048 floats (plain q copy)
#define CS2_OFF  18944              // 512
#define RED_OFF  19456              // 40
#define SMEM_FLOATS 19496           // ~78 KB -> 2 blocks/SM

typedef unsigned long long ull;

__device__ __forceinline__ ull fma2(ull a, ull b, ull c) {
    ull d;
    asm("fma.rn.f32x2 %0, %1, %2, %3;" : "=l"(d) : "l"(a), "l"(b), "l"(c));
    return d;
}
__device__ __forceinline__ float2 unpack2(ull v) {
    unsigned lo, hi;
    asm("mov.b64 {%0, %1}, %2;" : "=r"(lo), "=r"(hi) : "l"(v));
    return make_float2(__uint_as_float(lo), __uint_as_float(hi));
}
__device__ __forceinline__ ull pack2(float lo, float hi) {
    ull d;
    asm("mov.b64 %0, {%1, %2};" : "=l"(d) : "r"(__float_as_uint(lo)), "r"(__float_as_uint(hi)));
    return d;
}
__device__ __forceinline__ uint32_t smem_u32(const void* p) {
    uint32_t a;
    asm("{ .reg .u64 t; cvta.to.shared.u64 t, %1; cvt.u32.u64 %0, t; }" : "=r"(a) : "l"(p));
    return a;
}
#define CP_ASYNC16(dst, src, sz) \
    asm volatile("cp.async.cg.shared.global [%0], [%1], 16, %2;" \
                 :: "r"(dst), "l"(src), "r"(sz) : "memory")
#define CP_COMMIT()  asm volatile("cp.async.commit_group;" ::: "memory")
#define CP_WAIT1()   asm volatile("cp.async.wait_group 1;" ::: "memory")
#define CP_WAIT0()   asm volatile("cp.async.wait_group 0;" ::: "memory")

__device__ float g_mins[8192];
__device__ int   g_count;

extern __shared__ __align__(16) float smf[];

// cp.async staging of one chunk (16 rows x 512 floats), zero-fill past len
__device__ __forceinline__ void stage_async(const float* __restrict__ X, long long T,
                                            long long c0, int len, int tid, int dbase,
                                            uint32_t buf_u32)
{
    const int col  = tid & 127;          // 16B unit within row
    const int half = tid >> 7;           // 0..1
    int vb = len * 4 - col * 16;
    int sz = vb < 0 ? 0 : (vb > 16 ? 16 : vb);
    const char* gbase = (const char*)(X + c0) + (size_t)col * 16;
#pragma unroll
    for (int k = 0; k < 8; k++) {
        int dd = half + 2 * k;
        uint32_t daddr = buf_u32 + (uint32_t)(dd * XSTR * 4 + col * 16);
        const char* g = gbase + (long long)(dbase + dd) * T * 4;
        CP_ASYNC16(daddr, g, sz);
    }
}

// scalar fallback (misaligned c0)
__device__ __forceinline__ void stage_scalar(const float* __restrict__ X, long long T,
                                             long long c0, int len, int tid, int dbase,
                                             float* buf)
{
    for (int i = tid; i < DCH * TT; i += NT) {
        int dd = i >> 9;
        int t  = i & (TT - 1);
        buf[dd * XSTR + t] = (t < len) ? X[(long long)(dbase + dd) * T + c0 + t] : 0.f;
    }
}

__global__ __launch_bounds__(NT, 2)
void shapelet_kernel(const float* __restrict__ X,
                     const float* __restrict__ q,
                     const int* __restrict__ cumlens,
                     const float* __restrict__ lin_w,
                     const float* __restrict__ lin_b,
                     float* __restrict__ out,
                     long long T, int n_seg)
{
    float* Xs   = smf + XS_OFF;
    float* qs   = smf + QS_OFF;
    float* cs2p = smf + CS2_OFF;
    float* redf = smf + RED_OFF;
    float* part = smf;                    // aliases Xs (disjoint phases)
    const uint32_t xs_u32 = smem_u32(Xs);

    const int tid  = threadIdx.x;
    const int w    = tid >> 5;
    const int lane = tid & 31;
    const int t0   = (tid >> 2) * 8;      // 64 t-groups
    const int j0   = (tid & 3) * 8;       // 4 j-groups

    const int seg = blockIdx.x;
    const long long c0 = (long long)cumlens[seg];
    int len = cumlens[seg + 1] - (int)c0;
    if (len > TT) len = TT;
    if (len < 0) len = 0;

    const bool aligned = ((c0 & 3) == 0);

    // kick off chunk 0 copy immediately
    if (aligned) { stage_async(X, T, c0, len, tid, 0, xs_u32); CP_COMMIT(); }
    else         stage_scalar(X, T, c0, len, tid, 0, Xs);

    // zero the pad columns [512, 528) of all 32 rows (both buffers)
#pragma unroll
    for (int k = 0; k < 2; k++) {
        int i = tid + k * NT;             // 0..511
        int r = i >> 4, cc = i & 15;
        Xs[r * XSTR + 512 + cc] = 0.f;
    }

    // q copy + QQ
    float qq = 0.f;
#pragma unroll
    for (int k = 0; k < 8; k++) {
        int i = tid + k * NT;
        float v = q[i];
        qs[i] = v;
        qq = fmaf(v, v, qq);
    }
#pragma unroll
    for (int o = 16; o; o >>= 1) qq += __shfl_down_sync(0xffffffffu, qq, o);
    if (lane == 0) redf[w] = qq;
    __syncthreads();
    float QQ = 0.f;
#pragma unroll
    for (int ww = 0; ww < NT / 32; ww++) QQ += redf[ww];

    // ---- pipelined chunks ----
    ull accE[7], accO[7];
#pragma unroll
    for (int i = 0; i < 7; i++) { accE[i] = 0ull; accO[i] = 0ull; }

    float csA = 0.f, csB = 0.f;

#pragma unroll
    for (int c = 0; c < NCHUNK; c++) {
        if (c + 1 < NCHUNK) {
            if (aligned) {
                stage_async(X, T, c0, len, tid, (c + 1) * DCH,
                            xs_u32 + (uint32_t)(((c + 1) & 1) * DCH * XSTR * 4));
                CP_COMMIT();
            } else {
                stage_scalar(X, T, c0, len, tid, (c + 1) * DCH,
                             Xs + ((c + 1) & 1) * DCH * XSTR);
            }
        }
        if (aligned) { if (c + 1 < NCHUNK) CP_WAIT1(); else CP_WAIT0(); }
        __syncthreads();

        const float* xb = Xs + (c & 1) * DCH * XSTR;
        const float* qrow = qs + (c * DCH) * MLEN + j0;

        // column squared-sums (2 columns per thread)
        {
            float sA = csA, sB = csB;
#pragma unroll
            for (int dd = 0; dd < DCH; dd++) {
                float v  = xb[dd * XSTR + tid];
                float v2 = xb[dd * XSTR + tid + NT];
                sA = fmaf(v, v, sA);
                sB = fmaf(v2, v2, sB);
            }
            csA = sA; csB = sB;
        }

        // diagonal-pair GEMM over 16 d-rows
#pragma unroll 8
        for (int dd = 0; dd < DCH; dd++) {
            const float* xr = xb + dd * XSTR + t0;
            ulonglong2 xa = *(const ulonglong2*)xr;
            ulonglong2 xc = *(const ulonglong2*)(xr + 4);
            float x8 = xr[8];
            const ulonglong2 qv0 = *(const ulonglong2*)(qrow + dd * MLEN);
            const ulonglong2 qv1 = *(const ulonglong2*)(qrow + dd * MLEN + 4);

            ull xp[4] = { xa.x, xa.y, xc.x, xc.y };
            float2 p0 = unpack2(xa.x), p1 = unpack2(xa.y);
            float2 p2 = unpack2(xc.x), p3 = unpack2(xc.y);
            ull sp[4] = { pack2(p0.y, p1.x), pack2(p1.y, p2.x),
                          pack2(p2.y, p3.x), pack2(p3.y, x8) };
            ull qp[4] = { qv0.x, qv0.y, qv1.x, qv1.y };

#pragma unroll
            for (int i = 0; i < 4; i++) {
#pragma unroll
                for (int k = 0; k < 4; k++) {
                    accE[i - k + 3] = fma2(xp[i], qp[k], accE[i - k + 3]);
                    accO[i - k + 3] = fma2(sp[i], qp[k], accO[i - k + 3]);
                }
            }
        }
        __syncthreads();   // buffer (c&1) overwritten next iteration
    }

    cs2p[tid] = csA;
    cs2p[tid + NT] = csB;

    // write diagonal buckets to part table (slot = local delta + 6, 0..13)
#pragma unroll
    for (int e = 0; e < 7; e++) {
        float2 u = unpack2(accE[e]);
        part[tid * PSTRIDE + 2 * e] = u.x + u.y;        // delta 2(e-3) -> slot 2e
    }
#pragma unroll
    for (int o = 0; o < 7; o++) {
        float2 u = unpack2(accO[o]);
        part[tid * PSTRIDE + 2 * o + 1] = u.x + u.y;    // delta 2(o-3)+1 -> slot 2o+1
    }
    __syncthreads();

    // gather QX[p], dist, min (2 windows per thread)
    const int nwin = len - MLEN + 1;
    float lmin = 3e38f;
#pragma unroll
    for (int wnd = 0; wnd < 2; wnd++) {
        const int p = tid + wnd * NT;
        if (p < nwin) {
            float xx = 0.f;
#pragma unroll
            for (int j = 0; j < MLEN; j++) xx += cs2p[p + j];
            float qx = 0.f;
#pragma unroll
            for (int b = 0; b < 4; b++) {
                int base = p + 8 * b + 6;       // slot = base - 8a in [0,13]
                int a1 = base >> 3;
                int a0 = (base - 6) >> 3;
                if (a1 > 63) a1 = 63;
                for (int a = a0; a <= a1; a++)
                    qx += part[(a * 4 + b) * PSTRIDE + base - 8 * a];
            }
            lmin = fminf(lmin, QQ + xx - 2.f * qx);
        }
    }
#pragma unroll
    for (int o = 16; o; o >>= 1) lmin = fminf(lmin, __shfl_down_sync(0xffffffffu, lmin, o));
    __syncthreads();
    if (lane == 0) redf[w] = lmin;
    __syncthreads();
    if (tid == 0) {
        float m = redf[0];
#pragma unroll
        for (int ww = 1; ww < NT / 32; ww++) m = fminf(m, redf[ww]);
        g_mins[seg] = m;
    }

    // ---- last-block-done epilogue ----
    int* flagp = (int*)(redf + 33);
    __threadfence();
    __syncthreads();
    if (tid == 0) {
        int old = atomicAdd(&g_count, 1);
        *flagp = (old == gridDim.x - 1) ? 1 : 0;
    }
    __syncthreads();
    if (!*flagp) return;
    __threadfence();

    float lo = 3e38f, hi = -3e38f;
    for (int i = tid; i < n_seg; i += NT) {
        float v = g_mins[i];
        lo = fminf(lo, v);
        hi = fmaxf(hi, v);
    }
#pragma unroll
    for (int o = 16; o; o >>= 1) {
        lo = fminf(lo, __shfl_down_sync(0xffffffffu, lo, o));
        hi = fmaxf(hi, __shfl_down_sync(0xffffffffu, hi, o));
    }
    __syncthreads();
    if (lane == 0) { redf[w] = lo; redf[16 + w] = hi; }
    __syncthreads();
    if (tid == 0) {
        float l = redf[0], h = redf[16];
#pragma unroll
        for (int ww = 1; ww < NT / 32; ww++) { l = fminf(l, redf[ww]); h = fmaxf(h, redf[16 + ww]); }
        redf[34] = l; redf[35] = h;
        g_count = 0;   // self-reset for next graph replay
    }
    __syncthreads();
    const float flo = redf[34], fhi = redf[35];
    const float w0 = lin_w[0], w1 = lin_w[1];
    const float b0 = lin_b[0], b1 = lin_b[1];
    const float inv = 1.f / (fhi - flo + 1e-16f);
    for (int i = tid; i < n_seg; i += NT) {
        float s = (g_mins[i] - flo) * inv;
        out[2 * i]     = fmaf(s, w0, b0);
        out[2 * i + 1] = fmaf(s, w1, b1);
    }
}

extern "C" void kernel_launch(void* const* d_in, const int* in_sizes, int n_in,
                              void* d_out, int out_size)
{
    const float* X   = (const float*)d_in[0];
    const float* q   = (const float*)d_in[1];
    const float* lw  = (const float*)d_in[2];
    const float* lb  = (const float*)d_in[3];
    const int*   cum = (const int*)d_in[4];

    const int n_seg = in_sizes[4] - 1;
    const long long T = (long long)in_sizes[0] / DFEAT;

    const size_t smem = SMEM_FLOATS * sizeof(float);
    cudaFuncSetAttribute(shapelet_kernel,
                         cudaFuncAttributeMaxDynamicSharedMemorySize, (int)smem);

    shapelet_kernel<<<n_seg, NT, smem>>>(X, q, cum, lw, lb, (float*)d_out, T, n_seg);
}

// round 6
// speedup vs baseline: 1.7099x; 1.0173x over previous
#include <cuda_runtime.h>
#include <cstdint>

// ShapeletNet via Ampere-style mma.sync (HMMA) bf16-split GEMM.
// S[t][j] = <X[:,t], q[:,j]>, computed in 4 chunks of 16 d-values.
// Per chunk: A row t = [bf16hi(x) 16d | bf16lo(x) 16d] (32 bf16 = 64B),
//   pass1 (2 k16-steps): B = [qh|qh]  -> xh*qh + xl*qh
//   pass2 (1 k16-step) : B = [ql|ql]  -> xh*ql      (xl*ql dropped, ~2^-16)
// dist[p] = QQ + XX[p] - 2*QX[p]; QX[p] = sum_j S[p+j][j]; per-segment min;
// last-done block: minmax scale + Linear(1,2).

#define DFEAT 64
#define MLEN 32
#define TT 512
#define NT 512
#define DCH 16
#define NCHUNK 4
#define SSTRIDE 33

// byte offsets in dynamic smem
#define XB_OFF   0          // 2 x 32KB chunk buffers (512 rows x 64B)
#define QB_OFF   65536      // 4 chunks x (B1 2KB + B2 2KB) = 16KB
#define CS2_OFF  81920      // 512 f32
#define RED_OFF  83968      // 40 f32
#define SMEM_BYTES 84352
// Sbuf (512*33*4 = 67584B) aliases XB+QB after mma is done

__device__ float g_mins[8192];
__device__ int   g_count;

extern __shared__ __align__(1024) float smf[];

__device__ __forceinline__ uint32_t smem_u32(const void* p) {
    uint32_t a;
    asm("{ .reg .u64 t; cvta.to.shared.u64 t, %1; cvt.u32.u64 %0, t; }" : "=r"(a) : "l"(p));
    return a;
}
// pack: result.hi = bf16(a), result.lo = bf16(b)
__device__ __forceinline__ uint32_t packbf(float a, float b) {
    uint32_t r;
    asm("cvt.rn.bf16x2.f32 %0, %1, %2;" : "=r"(r) : "f"(a), "f"(b));
    return r;
}
#define STS128(r0, r1, r2, r3, addr) \
    asm volatile("st.shared.v4.b32 [%0], {%1, %2, %3, %4};" \
                 :: "r"(addr), "r"(r0), "r"(r1), "r"(r2), "r"(r3) : "memory")

__device__ __forceinline__ void ldmA(uint32_t* a, uint32_t addr) {
    asm volatile("ldmatrix.sync.aligned.m8n8.x4.shared.b16 {%0,%1,%2,%3}, [%4];"
                 : "=r"(a[0]), "=r"(a[1]), "=r"(a[2]), "=r"(a[3]) : "r"(addr));
}
__device__ __forceinline__ void ldmB(uint32_t* b, uint32_t addr) {
    asm volatile("ldmatrix.sync.aligned.m8n8.x2.shared.b16 {%0,%1}, [%2];"
                 : "=r"(b[0]), "=r"(b[1]) : "r"(addr));
}
__device__ __forceinline__ void mma16816(float* c, const uint32_t* a, const uint32_t* b) {
    asm volatile("mma.sync.aligned.m16n8k16.row.col.f32.bf16.bf16.f32 "
                 "{%0,%1,%2,%3}, {%4,%5,%6,%7}, {%8,%9}, {%0,%1,%2,%3};"
                 : "+f"(c[0]), "+f"(c[1]), "+f"(c[2]), "+f"(c[3])
                 : "r"(a[0]), "r"(a[1]), "r"(a[2]), "r"(a[3]), "r"(b[0]), "r"(b[1]));
}
// swizzled granule position within a 64B row
__device__ __forceinline__ uint32_t gpos(int r, int g) {
    return (uint32_t)(g ^ ((r >> 1) & 3));
}

__global__ __launch_bounds__(NT, 2)
void shapelet_kernel(const float* __restrict__ X,
                     const float* __restrict__ q,
                     const int* __restrict__ cumlens,
                     const float* __restrict__ lin_w,
                     const float* __restrict__ lin_b,
                     float* __restrict__ out,
                     long long T, int n_seg)
{
    const uint32_t smb = smem_u32(smf);
    float* cs2p = smf + CS2_OFF / 4;
    float* redf = smf + RED_OFF / 4;
    float* Sbuf = smf;                      // alias, used post-GEMM

    const int tid  = threadIdx.x;
    const int w    = tid >> 5;
    const int lane = tid & 31;

    const int seg = blockIdx.x;
    const long long c0 = (long long)cumlens[seg];
    int len = cumlens[seg + 1] - (int)c0;
    if (len > TT) len = TT;
    if (len < 0) len = 0;

    // ---- Q staging (warp 0: thread j = lane owns B row j) + QQ ----
    if (w == 0) {
        float qq = 0.f;
        const int j = lane;
#pragma unroll
        for (int c = 0; c < NCHUNK; c++) {
            uint32_t h[4], l[4];
#pragma unroll
            for (int pr = 0; pr < 8; pr++) {
                int d = 16 * c + 2 * pr;
                float qe = q[d * MLEN + j];
                float qo = q[(d + 1) * MLEN + j];
                qq = fmaf(qe, qe, qq);
                qq = fmaf(qo, qo, qq);
                uint32_t hp = packbf(qo, qe);
                float fe = __uint_as_float(hp << 16);
                float fo = __uint_as_float(hp & 0xffff0000u);
                h[pr >> 1] = (pr & 1) ? h[pr >> 1] : 0;   // init slot
                // store into h[pr>>1] halves: pr even -> will be lo pair; handled below
                // simpler: accumulate into arrays
                if ((pr & 1) == 0) { h[pr >> 1] = hp; l[pr >> 1] = packbf(qo - fo, qe - fe); }
                else {
                    // second pair of this granule-half: shift into upper b32
                    // (granule = 4 b32 = 8 bf16 = 8 d; pairs pr 0..3 -> granule0, 4..7 -> granule1)
                    h[pr >> 1] = hp; l[pr >> 1] = packbf(qo - fo, qe - fe);
                }
            }
            // NOTE: rebuild cleanly: granule g holds pairs 4g..4g+3
            // redo loads to keep code simple & correct
            uint32_t hg[2][4], lg[2][4];
#pragma unroll
            for (int g = 0; g < 2; g++) {
#pragma unroll
                for (int k = 0; k < 4; k++) {
                    int d = 16 * c + 8 * g + 2 * k;
                    float qe = q[d * MLEN + j];
                    float qo = q[(d + 1) * MLEN + j];
                    uint32_t hp = packbf(qo, qe);
                    float fe = __uint_as_float(hp << 16);
                    float fo = __uint_as_float(hp & 0xffff0000u);
                    hg[g][k] = hp;
                    lg[g][k] = packbf(qo - fo, qe - fe);
                }
            }
            uint32_t b1 = smb + QB_OFF + (uint32_t)c * 4096u + (uint32_t)j * 64u;
            uint32_t b2 = b1 + 2048u * 32u / 32u + 0u;      // placeholder
            b2 = smb + QB_OFF + (uint32_t)c * 4096u + 2048u + (uint32_t)j * 64u;
            // B1 = [qh g0 | qh g1 | qh g0 | qh g1]
            STS128(hg[0][0], hg[0][1], hg[0][2], hg[0][3], b1 + gpos(j, 0) * 16u);
            STS128(hg[1][0], hg[1][1], hg[1][2], hg[1][3], b1 + gpos(j, 1) * 16u);
            STS128(hg[0][0], hg[0][1], hg[0][2], hg[0][3], b1 + gpos(j, 2) * 16u);
            STS128(hg[1][0], hg[1][1], hg[1][2], hg[1][3], b1 + gpos(j, 3) * 16u);
            // B2 = [ql g0 | ql g1 | ql g0 | ql g1]
            STS128(lg[0][0], lg[0][1], lg[0][2], lg[0][3], b2 + gpos(j, 0) * 16u);
            STS128(lg[1][0], lg[1][1], lg[1][2], lg[1][3], b2 + gpos(j, 1) * 16u);
            STS128(lg[0][0], lg[0][1], lg[0][2], lg[0][3], b2 + gpos(j, 2) * 16u);
            STS128(lg[1][0], lg[1][1], lg[1][2], lg[1][3], b2 + gpos(j, 3) * 16u);
        }
#pragma unroll
        for (int o = 16; o; o >>= 1) qq += __shfl_down_sync(0xffffffffu, qq, o);
        if (lane == 0) redf[36] = qq;
    }

    // ---- accumulators: warp owns t in [32w, 32w+32): 2 m-tiles x 4 n-tiles ----
    float acc[2][4][4];
#pragma unroll
    for (int m = 0; m < 2; m++)
#pragma unroll
        for (int n = 0; n < 4; n++)
#pragma unroll
            for (int k = 0; k < 4; k++) acc[m][n][k] = 0.f;

    float cs = 0.f;
    const bool ok = tid < len;
    const float* xcol = X + c0 + tid;

    for (int c = 0; c < NCHUNK; c++) {
        // ---- stage chunk c: thread owns A row t = tid ----
        {
            uint32_t hg[2][4], lg[2][4];
#pragma unroll
            for (int g = 0; g < 2; g++) {
#pragma unroll
                for (int k = 0; k < 4; k++) {
                    int d = 16 * c + 8 * g + 2 * k;
                    float xe = ok ? xcol[(long long)d * T] : 0.f;
                    float xo = ok ? xcol[(long long)(d + 1) * T] : 0.f;
                    cs = fmaf(xe, xe, cs);
                    cs = fmaf(xo, xo, cs);
                    uint32_t hp = packbf(xo, xe);
                    float fe = __uint_as_float(hp << 16);
                    float fo = __uint_as_float(hp & 0xffff0000u);
                    hg[g][k] = hp;
                    lg[g][k] = packbf(xo - fo, xe - fe);
                }
            }
            uint32_t row = smb + XB_OFF + (uint32_t)((c & 1) * 32768) + (uint32_t)tid * 64u;
            STS128(hg[0][0], hg[0][1], hg[0][2], hg[0][3], row + gpos(tid, 0) * 16u);
            STS128(hg[1][0], hg[1][1], hg[1][2], hg[1][3], row + gpos(tid, 1) * 16u);
            STS128(lg[0][0], lg[0][1], lg[0][2], lg[0][3], row + gpos(tid, 2) * 16u);
            STS128(lg[1][0], lg[1][1], lg[1][2], lg[1][3], row + gpos(tid, 3) * 16u);
        }
        __syncthreads();

        // ---- mma over this chunk ----
        const uint32_t xb  = smb + XB_OFF + (uint32_t)((c & 1) * 32768);
        const uint32_t qb1 = smb + QB_OFF + (uint32_t)c * 4096u;
        const uint32_t qb2 = qb1 + 2048u;
        const int l15 = lane & 15;

#pragma unroll
        for (int ks = 0; ks < 2; ks++) {
            const int gb = 2 * ks;
            uint32_t B1[4][2], B2[4][2];
#pragma unroll
            for (int n = 0; n < 4; n++) {
                int r = 8 * n + (l15 & 7);
                int g = gb + (l15 >> 3);
                ldmB(B1[n], qb1 + (uint32_t)r * 64u + gpos(r, g) * 16u);
                if (ks == 0)
                    ldmB(B2[n], qb2 + (uint32_t)r * 64u + gpos(r, g) * 16u);
            }
#pragma unroll
            for (int m = 0; m < 2; m++) {
                uint32_t A[4];
                int r = 32 * w + 16 * m + l15;
                int g = gb + (lane >> 4);
                ldmA(A, xb + (uint32_t)r * 64u + gpos(r, g) * 16u);
#pragma unroll
                for (int n = 0; n < 4; n++) mma16816(acc[m][n], A, B1[n]);
                if (ks == 0) {
#pragma unroll
                    for (int n = 0; n < 4; n++) mma16816(acc[m][n], A, B2[n]);
                }
            }
        }
        __syncthreads();   // buffer reuse / next stage
    }

    cs2p[tid] = cs;
    const float QQ = redf[36];
    __syncthreads();       // everyone done with mma inputs; Sbuf alias safe

    // ---- scatter S fragments to Sbuf[512][33] ----
    {
        const int rbase = 32 * w + (lane >> 2);
        const int cbase = 2 * (lane & 3);
#pragma unroll
        for (int m = 0; m < 2; m++) {
#pragma unroll
            for (int n = 0; n < 4; n++) {
                int r = rbase + 16 * m;
                int cc = cbase + 8 * n;
                Sbuf[r * SSTRIDE + cc]           = acc[m][n][0];
                Sbuf[r * SSTRIDE + cc + 1]       = acc[m][n][1];
                Sbuf[(r + 8) * SSTRIDE + cc]     = acc[m][n][2];
                Sbuf[(r + 8) * SSTRIDE + cc + 1] = acc[m][n][3];
            }
        }
    }
    __syncthreads();

    // ---- gather: QX[p], dist, segment min ----
    const int nwin = len - MLEN + 1;
    float lmin = 3e38f;
    if (tid < nwin) {
        float qx = 0.f, xx = 0.f;
#pragma unroll
        for (int j = 0; j < MLEN; j++) {
            qx += Sbuf[(tid + j) * SSTRIDE + j];
            xx += cs2p[tid + j];
        }
        lmin = QQ + xx - 2.f * qx;
    }
#pragma unroll
    for (int o = 16; o; o >>= 1) lmin = fminf(lmin, __shfl_down_sync(0xffffffffu, lmin, o));
    __syncthreads();
    if (lane == 0) redf[w] = lmin;
    __syncthreads();
    if (tid == 0) {
        float m = redf[0];
#pragma unroll
        for (int ww = 1; ww < NT / 32; ww++) m = fminf(m, redf[ww]);
        g_mins[seg] = m;
    }

    // ---- last-block-done epilogue ----
    int* flagp = (int*)(redf + 33);
    __threadfence();
    __syncthreads();
    if (tid == 0) {
        int old = atomicAdd(&g_count, 1);
        *flagp = (old == gridDim.x - 1) ? 1 : 0;
    }
    __syncthreads();
    if (!*flagp) return;
    __threadfence();

    float lo = 3e38f, hi = -3e38f;
    for (int i = tid; i < n_seg; i += NT) {
        float v = g_mins[i];
        lo = fminf(lo, v);
        hi = fmaxf(hi, v);
    }
#pragma unroll
    for (int o = 16; o; o >>= 1) {
        lo = fminf(lo, __shfl_down_sync(0xffffffffu, lo, o));
        hi = fmaxf(hi, __shfl_down_sync(0xffffffffu, hi, o));
    }
    __syncthreads();
    if (lane == 0) { redf[w] = lo; redf[16 + w] = hi; }
    __syncthreads();
    if (tid == 0) {
        float l = redf[0], h = redf[16];
#pragma unroll
        for (int ww = 1; ww < NT / 32; ww++) { l = fminf(l, redf[ww]); h = fmaxf(h, redf[16 + ww]); }
        redf[34] = l; redf[35] = h;
        g_count = 0;
    }
    __syncthreads();
    const float flo = redf[34], fhi = redf[35];
    const float w0 = lin_w[0], w1 = lin_w[1];
    const float b0 = lin_b[0], b1 = lin_b[1];
    const float inv = 1.f / (fhi - flo + 1e-16f);
    for (int i = tid; i < n_seg; i += NT) {
        float s = (g_mins[i] - flo) * inv;
        out[2 * i]     = fmaf(s, w0, b0);
        out[2 * i + 1] = fmaf(s, w1, b1);
    }
}

extern "C" void kernel_launch(void* const* d_in, const int* in_sizes, int n_in,
                              void* d_out, int out_size)
{
    const float* X   = (const float*)d_in[0];
    const float* q   = (const float*)d_in[1];
    const float* lw  = (const float*)d_in[2];
    const float* lb  = (const float*)d_in[3];
    const int*   cum = (const int*)d_in[4];

    const int n_seg = in_sizes[4] - 1;
    const long long T = (long long)in_sizes[0] / DFEAT;

    cudaFuncSetAttribute(shapelet_kernel,
                         cudaFuncAttributeMaxDynamicSharedMemorySize, SMEM_BYTES);

    shapelet_kernel<<<n_seg, NT, SMEM_BYTES>>>(X, q, cum, lw, lb, (float*)d_out, T, n_seg);
}

// round 7
// speedup vs baseline: 2.2061x; 1.2902x over previous
#include <cuda_runtime.h>
#include <cstdint>

// ShapeletNet via HMMA (mma.sync m16n8k16 bf16) with cp.async pipelined staging.
// 8 chunks of 8 d-values. A row t (k16) = [bf16hi(x) 8d | bf16lo(x) 8d].
//   B1 = [qh|qh] -> xh*qh + xl*qh ;  B2 = [ql|0] -> xh*ql   (xl*ql dropped)
// dist[p] = QQ + XX[p] - 2*QX[p]; QX[p] = sum_j S[p+j][j]; per-segment min;
// last-done block: minmax scale + Linear(1,2).

#define DFEAT 64
#define MLEN 32
#define TT 512
#define NT 512
#define DCH 8
#define NCHUNK 8
#define SSTRIDE 33
#define ASTR 48         // A row stride in bytes (conflict-free ldmatrix)

// byte offsets in dynamic smem
#define XF_OFF   0          // 2 x 16KB f32 staging buffers
#define A_OFF    32768      // 512 rows x 48B = 24576
#define QB_OFF   57344      // 8 chunks x (B1 2KB + B2 2KB) = 32768
#define CS2_OFF  90112      // 512 f32
#define RED_OFF  92160      // 48 f32
#define SMEM_BYTES 92416
// Sbuf (512*33*4 = 67584B) aliases XF+A+QB-head after GEMM

__device__ float g_mins[8192];
__device__ int   g_count;

extern __shared__ __align__(1024) float smf[];

__device__ __forceinline__ uint32_t smem_u32(const void* p) {
    uint32_t a;
    asm("{ .reg .u64 t; cvta.to.shared.u64 t, %1; cvt.u32.u64 %0, t; }" : "=r"(a) : "l"(p));
    return a;
}
// pack: result.hi = bf16(a), result.lo = bf16(b)
__device__ __forceinline__ uint32_t packbf(float a, float b) {
    uint32_t r;
    asm("cvt.rn.bf16x2.f32 %0, %1, %2;" : "=r"(r) : "f"(a), "f"(b));
    return r;
}
#define STS128(r0, r1, r2, r3, addr) \
    asm volatile("st.shared.v4.b32 [%0], {%1, %2, %3, %4};" \
                 :: "r"(addr), "r"(r0), "r"(r1), "r"(r2), "r"(r3) : "memory")
#define CP_ASYNC16(dst, src, sz) \
    asm volatile("cp.async.cg.shared.global [%0], [%1], 16, %2;" \
                 :: "r"(dst), "l"(src), "r"(sz) : "memory")
#define CP_COMMIT()  asm volatile("cp.async.commit_group;" ::: "memory")
#define CP_WAIT1()   asm volatile("cp.async.wait_group 1;" ::: "memory")
#define CP_WAIT0()   asm volatile("cp.async.wait_group 0;" ::: "memory")

__device__ __forceinline__ void ldmA(uint32_t* a, uint32_t addr) {
    asm volatile("ldmatrix.sync.aligned.m8n8.x4.shared.b16 {%0,%1,%2,%3}, [%4];"
                 : "=r"(a[0]), "=r"(a[1]), "=r"(a[2]), "=r"(a[3]) : "r"(addr));
}
__device__ __forceinline__ void ldmB(uint32_t* b, uint32_t addr) {
    asm volatile("ldmatrix.sync.aligned.m8n8.x2.shared.b16 {%0,%1}, [%2];"
                 : "=r"(b[0]), "=r"(b[1]) : "r"(addr));
}
__device__ __forceinline__ void mma16816(float* c, const uint32_t* a, const uint32_t* b) {
    asm volatile("mma.sync.aligned.m16n8k16.row.col.f32.bf16.bf16.f32 "
                 "{%0,%1,%2,%3}, {%4,%5,%6,%7}, {%8,%9}, {%0,%1,%2,%3};"
                 : "+f"(c[0]), "+f"(c[1]), "+f"(c[2]), "+f"(c[3])
                 : "r"(a[0]), "r"(a[1]), "r"(a[2]), "r"(a[3]), "r"(b[0]), "r"(b[1]));
}
// swizzled granule position within a 64B row (B buffers)
__device__ __forceinline__ uint32_t gpos(int r, int g) {
    return (uint32_t)(g ^ ((r >> 1) & 3));
}

// cp.async one chunk (8 rows x 512 f32), zero-fill past len
__device__ __forceinline__ void stage_async(const float* __restrict__ X, long long T,
                                            long long c0, int len, int tid, int dbase,
                                            uint32_t buf_u32)
{
    const int col = tid & 127;           // 16B unit
    const int r0  = tid >> 7;            // 0..3
    int vb = len * 4 - col * 16;
    int sz = vb < 0 ? 0 : (vb > 16 ? 16 : vb);
    const char* gb = (const char*)(X + c0) + (size_t)col * 16;
#pragma unroll
    for (int k = 0; k < 2; k++) {
        int dd = r0 + 4 * k;
        CP_ASYNC16(buf_u32 + (uint32_t)(dd * 2048 + col * 16),
                   gb + (long long)(dbase + dd) * T * 4, sz);
    }
}
__device__ __forceinline__ void stage_scalar(const float* __restrict__ X, long long T,
                                             long long c0, int len, int tid, int dbase,
                                             float* buf)
{
#pragma unroll
    for (int k = 0; k < 8; k++) {
        int i = tid + k * NT;
        int dd = i >> 9;
        int t  = i & 511;
        buf[i] = (t < len) ? X[(long long)(dbase + dd) * T + c0 + t] : 0.f;
    }
}

__global__ __launch_bounds__(NT, 2)
void shapelet_kernel(const float* __restrict__ X,
                     const float* __restrict__ q,
                     const int* __restrict__ cumlens,
                     const float* __restrict__ lin_w,
                     const float* __restrict__ lin_b,
                     float* __restrict__ out,
                     long long T, int n_seg)
{
    const uint32_t smb = smem_u32(smf);
    float* cs2p = smf + CS2_OFF / 4;
    float* redf = smf + RED_OFF / 4;
    float* Sbuf = smf;

    const int tid  = threadIdx.x;
    const int w    = tid >> 5;
    const int lane = tid & 31;
    const int l15  = lane & 15;

    const int seg = blockIdx.x;
    const long long c0 = (long long)cumlens[seg];
    int len = cumlens[seg + 1] - (int)c0;
    if (len > TT) len = TT;
    if (len < 0) len = 0;
    const bool aligned = ((c0 & 3) == 0);

    // ---- kick off chunk 0 copy ----
    if (aligned) { stage_async(X, T, c0, len, tid, 0, smb + XF_OFF); CP_COMMIT(); }
    else         stage_scalar(X, T, c0, len, tid, 0, smf);

    // ---- Q staging: warp w (w<8) builds B1+B2 for chunk w, + QQ ----
    if (w < 8) {
        const int j = lane;
        float qq = 0.f;
        uint32_t h[4], l[4];
#pragma unroll
        for (int k = 0; k < 4; k++) {
            int d = 8 * w + 2 * k;
            float qe = q[d * MLEN + j];
            float qo = q[(d + 1) * MLEN + j];
            qq = fmaf(qe, qe, qq);
            qq = fmaf(qo, qo, qq);
            uint32_t hp = packbf(qo, qe);
            float fe = __uint_as_float(hp << 16);
            float fo = __uint_as_float(hp & 0xffff0000u);
            h[k] = hp;
            l[k] = packbf(qo - fo, qe - fe);
        }
        uint32_t b1 = smb + QB_OFF + (uint32_t)w * 4096u + (uint32_t)j * 64u;
        uint32_t b2 = b1 + 2048u;
#pragma unroll
        for (int g = 0; g < 4; g++)
            STS128(h[0], h[1], h[2], h[3], b1 + gpos(j, g) * 16u);
        STS128(l[0], l[1], l[2], l[3], b2 + gpos(j, 0) * 16u);
        STS128(0u, 0u, 0u, 0u,          b2 + gpos(j, 1) * 16u);
        STS128(0u, 0u, 0u, 0u,          b2 + gpos(j, 2) * 16u);
        STS128(0u, 0u, 0u, 0u,          b2 + gpos(j, 3) * 16u);
#pragma unroll
        for (int o = 16; o; o >>= 1) qq += __shfl_down_sync(0xffffffffu, qq, o);
        if (lane == 0) redf[40 + w] = qq;
    }

    // ---- accumulators: warp owns t in [32w, 32w+32): 2 m-tiles x 4 n-tiles ----
    float acc[2][4][4];
#pragma unroll
    for (int m = 0; m < 2; m++)
#pragma unroll
        for (int n = 0; n < 4; n++)
#pragma unroll
            for (int k = 0; k < 4; k++) acc[m][n][k] = 0.f;

    float cs = 0.f;

    for (int c = 0; c < NCHUNK; c++) {
        // prefetch next chunk
        if (c + 1 < NCHUNK) {
            if (aligned) {
                stage_async(X, T, c0, len, tid, (c + 1) * DCH,
                            smb + XF_OFF + (uint32_t)(((c + 1) & 1) * 16384));
                CP_COMMIT();
            } else {
                stage_scalar(X, T, c0, len, tid, (c + 1) * DCH,
                             smf + ((c + 1) & 1) * 4096);
            }
        }
        if (aligned) { if (c + 1 < NCHUNK) CP_WAIT1(); else CP_WAIT0(); }
        __syncthreads();   // XF[c&1] visible; A free (prev MMA done); QB ready

        // ---- convert: f32 smem -> bf16 hi/lo A rows (thread = row t) ----
        {
            const float* xf = smf + (c & 1) * 4096;
            float xs[8];
#pragma unroll
            for (int r = 0; r < 8; r++) xs[r] = xf[r * 512 + tid];
            uint32_t h[4], l[4];
#pragma unroll
            for (int k = 0; k < 4; k++) {
                float xe = xs[2 * k], xo = xs[2 * k + 1];
                cs = fmaf(xe, xe, cs);
                cs = fmaf(xo, xo, cs);
                uint32_t hp = packbf(xo, xe);
                float fe = __uint_as_float(hp << 16);
                float fo = __uint_as_float(hp & 0xffff0000u);
                h[k] = hp;
                l[k] = packbf(xo - fo, xe - fe);
            }
            uint32_t row = smb + A_OFF + (uint32_t)tid * ASTR;
            STS128(h[0], h[1], h[2], h[3], row);
            STS128(l[0], l[1], l[2], l[3], row + 16u);
        }
        __syncthreads();   // A ready

        // ---- MMA chunk c ----
        {
            const uint32_t ab  = smb + A_OFF;
            const uint32_t qb1 = smb + QB_OFF + (uint32_t)c * 4096u;
            const uint32_t qb2 = qb1 + 2048u;

            uint32_t B1[4][2], B2[4][2];
#pragma unroll
            for (int n = 0; n < 4; n++) {
                int r = 8 * n + (l15 & 7);
                int g = l15 >> 3;
                ldmB(B1[n], qb1 + (uint32_t)r * 64u + gpos(r, g) * 16u);
                ldmB(B2[n], qb2 + (uint32_t)r * 64u + gpos(r, g) * 16u);
            }
#pragma unroll
            for (int m = 0; m < 2; m++) {
                uint32_t A[4];
                int r = 32 * w + 16 * m + l15;
                int g = lane >> 4;
                ldmA(A, ab + (uint32_t)r * ASTR + (uint32_t)g * 16u);
#pragma unroll
                for (int n = 0; n < 4; n++) {
                    mma16816(acc[m][n], A, B1[n]);
                    mma16816(acc[m][n], A, B2[n]);
                }
            }
        }
    }

    cs2p[tid] = cs;
    float QQ = 0.f;
#pragma unroll
    for (int k = 0; k < 8; k++) QQ += redf[40 + k];
    __syncthreads();       // all MMAs done; Sbuf alias safe

    // ---- scatter S fragments to Sbuf[512][33] ----
    {
        const int rbase = 32 * w + (lane >> 2);
        const int cbase = 2 * (lane & 3);
#pragma unroll
        for (int m = 0; m < 2; m++) {
#pragma unroll
            for (int n = 0; n < 4; n++) {
                int r = rbase + 16 * m;
                int cc = cbase + 8 * n;
                Sbuf[r * SSTRIDE + cc]           = acc[m][n][0];
                Sbuf[r * SSTRIDE + cc + 1]       = acc[m][n][1];
                Sbuf[(r + 8) * SSTRIDE + cc]     = acc[m][n][2];
                Sbuf[(r + 8) * SSTRIDE + cc + 1] = acc[m][n][3];
            }
        }
    }
    __syncthreads();

    // ---- gather: QX[p], dist, segment min ----
    const int nwin = len - MLEN + 1;
    float lmin = 3e38f;
    if (tid < nwin) {
        float qx = 0.f, xx = 0.f;
#pragma unroll
        for (int j = 0; j < MLEN; j++) {
            qx += Sbuf[(tid + j) * SSTRIDE + j];
            xx += cs2p[tid + j];
        }
        lmin = QQ + xx - 2.f * qx;
    }
#pragma unroll
    for (int o = 16; o; o >>= 1) lmin = fminf(lmin, __shfl_down_sync(0xffffffffu, lmin, o));
    __syncthreads();
    if (lane == 0) redf[w] = lmin;
    __syncthreads();
    if (tid == 0) {
        float m = redf[0];
#pragma unroll
        for (int ww = 1; ww < NT / 32; ww++) m = fminf(m, redf[ww]);
        g_mins[seg] = m;
    }

    // ---- last-block-done epilogue ----
    int* flagp = (int*)(redf + 33);
    __threadfence();
    __syncthreads();
    if (tid == 0) {
        int old = atomicAdd(&g_count, 1);
        *flagp = (old == gridDim.x - 1) ? 1 : 0;
    }
    __syncthreads();
    if (!*flagp) return;
    __threadfence();

    float lo = 3e38f, hi = -3e38f;
    for (int i = tid; i < n_seg; i += NT) {
        float v = g_mins[i];
        lo = fminf(lo, v);
        hi = fmaxf(hi, v);
    }
#pragma unroll
    for (int o = 16; o; o >>= 1) {
        lo = fminf(lo, __shfl_down_sync(0xffffffffu, lo, o));
        hi = fmaxf(hi, __shfl_down_sync(0xffffffffu, hi, o));
    }
    __syncthreads();
    if (lane == 0) { redf[w] = lo; redf[16 + w] = hi; }
    __syncthreads();
    if (tid == 0) {
        float l = redf[0], h = redf[16];
#pragma unroll
        for (int ww = 1; ww < NT / 32; ww++) { l = fminf(l, redf[ww]); h = fmaxf(h, redf[16 + ww]); }
        redf[34] = l; redf[35] = h;
        g_count = 0;
    }
    __syncthreads();
    const float flo = redf[34], fhi = redf[35];
    const float w0 = lin_w[0], w1 = lin_w[1];
    const float b0 = lin_b[0], b1 = lin_b[1];
    const float inv = 1.f / (fhi - flo + 1e-16f);
    for (int i = tid; i < n_seg; i += NT) {
        float s = (g_mins[i] - flo) * inv;
        out[2 * i]     = fmaf(s, w0, b0);
        out[2 * i + 1] = fmaf(s, w1, b1);
    }
}

extern "C" void kernel_launch(void* const* d_in, const int* in_sizes, int n_in,
                              void* d_out, int out_size)
{
    const float* X   = (const float*)d_in[0];
    const float* q   = (const float*)d_in[1];
    const float* lw  = (const float*)d_in[2];
    const float* lb  = (const float*)d_in[3];
    const int*   cum = (const int*)d_in[4];

    const int n_seg = in_sizes[4] - 1;
    const long long T = (long long)in_sizes[0] / DFEAT;

    cudaFuncSetAttribute(shapelet_kernel,
                         cudaFuncAttributeMaxDynamicSharedMemorySize, SMEM_BYTES);

    shapelet_kernel<<<n_seg, NT, SMEM_BYTES>>>(X, q, cum, lw, lb, (float*)d_out, T, n_seg);
}

// round 8
// speedup vs baseline: 2.4378x; 1.1050x over previous
#include <cuda_runtime.h>
#include <cstdint>

// ShapeletNet via HMMA bf16-split GEMM, fully warp-decoupled pipeline.
// All chunk-loop state (f32 staging XF, bf16 A tile) is WARP-PRIVATE:
//   - cp.async lane mapping copies exactly the 16B units the owning warp converts
//   - thread t converts A row t; warp w's ldmatrix reads rows [32w,32w+32)
// so the main loop uses only __syncwarp, no __syncthreads.
// Math: A row (k16) = [bf16hi(x) 8d | bf16lo(x) 8d];
//   B1 = [qh|qh] -> xh*qh + xl*qh ; B2 = [ql|0] -> xh*ql (xl*ql dropped ~2^-16)
// dist[p] = QQ + XX[p] - 2*QX[p]; per-segment min; last-done block: scale + Linear.

#define DFEAT 64
#define MLEN 32
#define TT 512
#define NT 512
#define DCH 8
#define NCHUNK 8
#define SSTRIDE 33
#define ASTR 48

// byte offsets in dynamic smem
#define XF_OFF   0          // 2 x 16KB staging: [buf][warp(1KB): r*128 + u*16]
#define A_OFF    32768      // 16 warps x 32 rows x 48B = 24576
#define QB_OFF   57344      // 8 chunks x (B1 2KB + B2 2KB) = 32768
#define CS2_OFF  90112      // 512 f32
#define RED_OFF  92160      // 64 f32
#define SMEM_BYTES 92416
// Sbuf (512*33*4 = 67584B) aliases XF+A+QB-head after GEMM

__device__ float g_mins[8192];
__device__ int   g_count;

extern __shared__ __align__(1024) float smf[];

__device__ __forceinline__ uint32_t smem_u32(const void* p) {
    uint32_t a;
    asm("{ .reg .u64 t; cvta.to.shared.u64 t, %1; cvt.u32.u64 %0, t; }" : "=r"(a) : "l"(p));
    return a;
}
// pack: result.hi = bf16(a), result.lo = bf16(b)
__device__ __forceinline__ uint32_t packbf(float a, float b) {
    uint32_t r;
    asm("cvt.rn.bf16x2.f32 %0, %1, %2;" : "=r"(r) : "f"(a), "f"(b));
    return r;
}
#define STS128(r0, r1, r2, r3, addr) \
    asm volatile("st.shared.v4.b32 [%0], {%1, %2, %3, %4};" \
                 :: "r"(addr), "r"(r0), "r"(r1), "r"(r2), "r"(r3) : "memory")
#define CP_ASYNC16(dst, src, sz) \
    asm volatile("cp.async.cg.shared.global [%0], [%1], 16, %2;" \
                 :: "r"(dst), "l"(src), "r"(sz) : "memory")
#define CP_COMMIT()  asm volatile("cp.async.commit_group;" ::: "memory")
#define CP_WAIT1()   asm volatile("cp.async.wait_group 1;" ::: "memory")
#define CP_WAIT0()   asm volatile("cp.async.wait_group 0;" ::: "memory")

__device__ __forceinline__ void ldmA(uint32_t* a, uint32_t addr) {
    asm volatile("ldmatrix.sync.aligned.m8n8.x4.shared.b16 {%0,%1,%2,%3}, [%4];"
                 : "=r"(a[0]), "=r"(a[1]), "=r"(a[2]), "=r"(a[3]) : "r"(addr));
}
__device__ __forceinline__ void ldmB(uint32_t* b, uint32_t addr) {
    asm volatile("ldmatrix.sync.aligned.m8n8.x2.shared.b16 {%0,%1}, [%2];"
                 : "=r"(b[0]), "=r"(b[1]) : "r"(addr));
}
__device__ __forceinline__ void mma16816(float* c, const uint32_t* a, const uint32_t* b) {
    asm volatile("mma.sync.aligned.m16n8k16.row.col.f32.bf16.bf16.f32 "
                 "{%0,%1,%2,%3}, {%4,%5,%6,%7}, {%8,%9}, {%0,%1,%2,%3};"
                 : "+f"(c[0]), "+f"(c[1]), "+f"(c[2]), "+f"(c[3])
                 : "r"(a[0]), "r"(a[1]), "r"(a[2]), "r"(a[3]), "r"(b[0]), "r"(b[1]));
}
__device__ __forceinline__ uint32_t gpos(int r, int g) {
    return (uint32_t)(g ^ ((r >> 1) & 3));
}

__global__ __launch_bounds__(NT, 2)
void shapelet_kernel(const float* __restrict__ X,
                     const float* __restrict__ q,
                     const int* __restrict__ cumlens,
                     const float* __restrict__ lin_w,
                     const float* __restrict__ lin_b,
                     float* __restrict__ out,
                     long long T, int n_seg)
{
    const uint32_t smb = smem_u32(smf);
    float* cs2p = smf + CS2_OFF / 4;
    float* redf = smf + RED_OFF / 4;
    float* Sbuf = smf;

    const int tid  = threadIdx.x;
    const int w    = tid >> 5;
    const int lane = tid & 31;
    const int l15  = lane & 15;

    const int seg = blockIdx.x;
    const long long c0 = (long long)cumlens[seg];
    int len = cumlens[seg + 1] - (int)c0;
    if (len > TT) len = TT;
    if (len < 0) len = 0;
    const bool aligned = ((c0 & 3) == 0);

    // warp-private staging geometry: lane l copies unit u = l&7 (16B = 4 floats
    // at t = 32w + 4u), rows r = l>>3 and r+4 of the chunk
    const int u_   = lane & 7;
    const int r_   = lane >> 3;
    const int tcol = 32 * w + 4 * u_;                 // float column of this unit
    const uint32_t xf_w = smb + XF_OFF + (uint32_t)w * 1024u
                        + (uint32_t)r_ * 128u + (uint32_t)u_ * 16u;
    int vb = len * 4 - tcol * 4;
    const int sz = vb < 0 ? 0 : (vb > 16 ? 16 : vb);
    const char* gsrc = (const char*)(X + c0 + tcol);

    // ---- stage chunk 0 (warp-private) ----
    if (aligned) {
        CP_ASYNC16(xf_w,        gsrc + (long long)(r_) * T * 4,     sz);
        CP_ASYNC16(xf_w + 512u, gsrc + (long long)(r_ + 4) * T * 4, sz);
        CP_COMMIT();
    } else {
#pragma unroll
        for (int rr = 0; rr < 2; rr++) {
            float v[4];
#pragma unroll
            for (int f = 0; f < 4; f++) {
                int t = tcol + f;
                v[f] = (t < len) ? X[(long long)(r_ + 4 * rr) * T + c0 + t] : 0.f;
            }
            STS128(__float_as_uint(v[0]), __float_as_uint(v[1]),
                   __float_as_uint(v[2]), __float_as_uint(v[3]), xf_w + 512u * rr);
        }
    }

    // ---- Q staging: warp w (w<8) builds B1+B2 for chunk w, + QQ partials ----
    if (w < 8) {
        const int j = lane;
        float qq = 0.f;
        uint32_t h[4], l[4];
#pragma unroll
        for (int k = 0; k < 4; k++) {
            int d = 8 * w + 2 * k;
            float qe = q[d * MLEN + j];
            float qo = q[(d + 1) * MLEN + j];
            qq = fmaf(qe, qe, qq);
            qq = fmaf(qo, qo, qq);
            uint32_t hp = packbf(qo, qe);
            float fe = __uint_as_float(hp << 16);
            float fo = __uint_as_float(hp & 0xffff0000u);
            h[k] = hp;
            l[k] = packbf(qo - fo, qe - fe);
        }
        uint32_t b1 = smb + QB_OFF + (uint32_t)w * 4096u + (uint32_t)j * 64u;
        uint32_t b2 = b1 + 2048u;
#pragma unroll
        for (int g = 0; g < 4; g++)
            STS128(h[0], h[1], h[2], h[3], b1 + gpos(j, g) * 16u);
        STS128(l[0], l[1], l[2], l[3], b2 + gpos(j, 0) * 16u);
        STS128(0u, 0u, 0u, 0u,          b2 + gpos(j, 1) * 16u);
        STS128(0u, 0u, 0u, 0u,          b2 + gpos(j, 2) * 16u);
        STS128(0u, 0u, 0u, 0u,          b2 + gpos(j, 3) * 16u);
#pragma unroll
        for (int o = 16; o; o >>= 1) qq += __shfl_down_sync(0xffffffffu, qq, o);
        if (lane == 0) redf[40 + w] = qq;
    }
    __syncthreads();     // QB + QQ visible to all; only block barrier before GEMM
    float QQ = 0.f;
#pragma unroll
    for (int k = 0; k < 8; k++) QQ += redf[40 + k];

    // ---- accumulators: warp owns t in [32w, 32w+32): 2 m x 4 n tiles ----
    float acc[2][4][4];
#pragma unroll
    for (int m = 0; m < 2; m++)
#pragma unroll
        for (int n = 0; n < 4; n++)
#pragma unroll
            for (int k = 0; k < 4; k++) acc[m][n][k] = 0.f;

    float cs = 0.f;
    const float* xfr = smf + (size_t)w * 256;          // warp's XF region (floats)
    const uint32_t arow = smb + A_OFF + (uint32_t)tid * ASTR;   // A row t = tid
    const uint32_t a_w  = smb + A_OFF + (uint32_t)(32 * w) * ASTR;

    for (int c = 0; c < NCHUNK; c++) {
        // prefetch next chunk (warp-private)
        if (c + 1 < NCHUNK) {
            if (aligned) {
                uint32_t dst = xf_w + (uint32_t)(((c + 1) & 1) * 16384);
                const char* g2 = gsrc + (long long)((c + 1) * DCH) * T * 4;
                CP_ASYNC16(dst,        g2 + (long long)(r_) * T * 4,     sz);
                CP_ASYNC16(dst + 512u, g2 + (long long)(r_ + 4) * T * 4, sz);
                CP_COMMIT();
            } else {
                uint32_t dst = xf_w + (uint32_t)(((c + 1) & 1) * 16384);
#pragma unroll
                for (int rr = 0; rr < 2; rr++) {
                    float v[4];
#pragma unroll
                    for (int f = 0; f < 4; f++) {
                        int t = tcol + f;
                        v[f] = (t < len) ?
                            X[(long long)((c + 1) * DCH + r_ + 4 * rr) * T + c0 + t] : 0.f;
                    }
                    STS128(__float_as_uint(v[0]), __float_as_uint(v[1]),
                           __float_as_uint(v[2]), __float_as_uint(v[3]), dst + 512u * rr);
                }
            }
        }
        if (aligned) { if (c + 1 < NCHUNK) CP_WAIT1(); else CP_WAIT0(); }
        __syncwarp();

        // ---- convert (warp-local): f32 -> bf16 hi/lo A row t = tid ----
        {
            const float* xf = xfr + ((c & 1) ? 4096 : 0);
            uint32_t h[4], l[4];
#pragma unroll
            for (int k = 0; k < 4; k++) {
                float xe = xf[(2 * k) * 32 + lane];
                float xo = xf[(2 * k + 1) * 32 + lane];
                cs = fmaf(xe, xe, cs);
                cs = fmaf(xo, xo, cs);
                uint32_t hp = packbf(xo, xe);
                float fe = __uint_as_float(hp << 16);
                float fo = __uint_as_float(hp & 0xffff0000u);
                h[k] = hp;
                l[k] = packbf(xo - fo, xe - fe);
            }
            STS128(h[0], h[1], h[2], h[3], arow);
            STS128(l[0], l[1], l[2], l[3], arow + 16u);
        }
        __syncwarp();

        // ---- MMA chunk c (warp-local A, shared read-only B) ----
        {
            const uint32_t qb1 = smb + QB_OFF + (uint32_t)c * 4096u;
            const uint32_t qb2 = qb1 + 2048u;
            uint32_t B1[4][2], B2[4][2];
#pragma unroll
            for (int n = 0; n < 4; n++) {
                int r = 8 * n + (l15 & 7);
                int g = l15 >> 3;
                ldmB(B1[n], qb1 + (uint32_t)r * 64u + gpos(r, g) * 16u);
                ldmB(B2[n], qb2 + (uint32_t)r * 64u + gpos(r, g) * 16u);
            }
#pragma unroll
            for (int m = 0; m < 2; m++) {
                uint32_t A[4];
                ldmA(A, a_w + (uint32_t)(16 * m + l15) * ASTR + (uint32_t)(lane >> 4) * 16u);
#pragma unroll
                for (int n = 0; n < 4; n++) {
                    mma16816(acc[m][n], A, B1[n]);
                    mma16816(acc[m][n], A, B2[n]);
                }
            }
        }
    }

    cs2p[tid] = cs;
    __syncthreads();       // all warps done with XF/A/QB; Sbuf alias safe

    // ---- scatter S fragments to Sbuf[512][33] ----
    {
        const int rbase = 32 * w + (lane >> 2);
        const int cbase = 2 * (lane & 3);
#pragma unroll
        for (int m = 0; m < 2; m++) {
#pragma unroll
            for (int n = 0; n < 4; n++) {
                int r = rbase + 16 * m;
                int cc = cbase + 8 * n;
                Sbuf[r * SSTRIDE + cc]           = acc[m][n][0];
                Sbuf[r * SSTRIDE + cc + 1]       = acc[m][n][1];
                Sbuf[(r + 8) * SSTRIDE + cc]     = acc[m][n][2];
                Sbuf[(r + 8) * SSTRIDE + cc + 1] = acc[m][n][3];
            }
        }
    }
    __syncthreads();

    // ---- gather: QX[p], dist, segment min ----
    const int nwin = len - MLEN + 1;
    float lmin = 3e38f;
    if (tid < nwin) {
        float qx = 0.f, xx = 0.f;
#pragma unroll
        for (int j = 0; j < MLEN; j++) {
            qx += Sbuf[(tid + j) * SSTRIDE + j];
            xx += cs2p[tid + j];
        }
        lmin = QQ + xx - 2.f * qx;
    }
#pragma unroll
    for (int o = 16; o; o >>= 1) lmin = fminf(lmin, __shfl_down_sync(0xffffffffu, lmin, o));
    __syncthreads();
    if (lane == 0) redf[w] = lmin;
    __syncthreads();
    if (tid == 0) {
        float m = redf[0];
#pragma unroll
        for (int ww = 1; ww < NT / 32; ww++) m = fminf(m, redf[ww]);
        g_mins[seg] = m;
    }

    // ---- last-block-done epilogue ----
    int* flagp = (int*)(redf + 33);
    __threadfence();
    __syncthreads();
    if (tid == 0) {
        int old = atomicAdd(&g_count, 1);
        *flagp = (old == gridDim.x - 1) ? 1 : 0;
    }
    __syncthreads();
    if (!*flagp) return;
    __threadfence();

    float lo = 3e38f, hi = -3e38f;
    for (int i = tid; i < n_seg; i += NT) {
        float v = g_mins[i];
        lo = fminf(lo, v);
        hi = fmaxf(hi, v);
    }
#pragma unroll
    for (int o = 16; o; o >>= 1) {
        lo = fminf(lo, __shfl_down_sync(0xffffffffu, lo, o));
        hi = fmaxf(hi, __shfl_down_sync(0xffffffffu, hi, o));
    }
    __syncthreads();
    if (lane == 0) { redf[w] = lo; redf[16 + w] = hi; }
    __syncthreads();
    if (tid == 0) {
        float l = redf[0], h = redf[16];
#pragma unroll
        for (int ww = 1; ww < NT / 32; ww++) { l = fminf(l, redf[ww]); h = fmaxf(h, redf[16 + ww]); }
        redf[34] = l; redf[35] = h;
        g_count = 0;
    }
    __syncthreads();
    const float flo = redf[34], fhi = redf[35];
    const float w0 = lin_w[0], w1 = lin_w[1];
    const float b0 = lin_b[0], b1 = lin_b[1];
    const float inv = 1.f / (fhi - flo + 1e-16f);
    for (int i = tid; i < n_seg; i += NT) {
        float s = (g_mins[i] - flo) * inv;
        out[2 * i]     = fmaf(s, w0, b0);
        out[2 * i + 1] = fmaf(s, w1, b1);
    }
}

extern "C" void kernel_launch(void* const* d_in, const int* in_sizes, int n_in,
                              void* d_out, int out_size)
{
    const float* X   = (const float*)d_in[0];
    const float* q   = (const float*)d_in[1];
    const float* lw  = (const float*)d_in[2];
    const float* lb  = (const float*)d_in[3];
    const int*   cum = (const int*)d_in[4];

    const int n_seg = in_sizes[4] - 1;
    const long long T = (long long)in_sizes[0] / DFEAT;

    cudaFuncSetAttribute(shapelet_kernel,
                         cudaFuncAttributeMaxDynamicSharedMemorySize, SMEM_BYTES);

    shapelet_kernel<<<n_seg, NT, SMEM_BYTES>>>(X, q, cum, lw, lb, (float*)d_out, T, n_seg);
}